// round 3
// baseline (speedup 1.0000x reference)
#include <cuda_runtime.h>

#define XS 128
#define BATCH 8
#define GRID_ELEMS (BATCH * XS * XS * XS)   // 16,777,216 floats = 67 MB (fits L2)

__device__ float g_grid[GRID_ELEMS];

// ---------------------------------------------------------------------------
// Kernel 1: scatter-add, 4 points per thread.
// 12 ints per 4 points -> 3x int4, values -> 1x float4.
// __ldcs: stream indices/values through L2 without evicting the grid.
// ---------------------------------------------------------------------------
__global__ void scatter_kernel(const int4* __restrict__ idx4,
                               const float4* __restrict__ val4) {
    int t = blockIdx.x * blockDim.x + threadIdx.x;   // 0 .. 524287
    int b = t >> 16;                                 // 65536 threads per batch
    int4 a = __ldcs(idx4 + 3 * t);                   // x0 y0 z0 x1
    int4 c = __ldcs(idx4 + 3 * t + 1);               // y1 z1 x2 y2
    int4 e = __ldcs(idx4 + 3 * t + 2);               // z2 x3 y3 z3
    float4 v = __ldcs(val4 + t);
    float* gb = g_grid + (b << 21);
    atomicAdd(gb + ((a.x << 14) | (a.y << 7) | a.z), v.x);
    atomicAdd(gb + ((a.w << 14) | (c.x << 7) | c.y), v.y);
    atomicAdd(gb + ((c.z << 14) | (c.w << 7) | e.x), v.z);
    atomicAdd(gb + ((e.y << 14) | (e.z << 7) | e.w), v.w);
}

// ---------------------------------------------------------------------------
// Kernel 2: fused TV + MSE reduction.
// Block = 256 threads = 8 j-rows x 32 z-quads (full z row per warp).
// Loops over 16 i-planes (+1 halo). x-diffs from prev-plane register,
// z-seam via shfl (quad index == lane index), y-diffs via double-buffered
// shared (+1 halo row for jl==7). Grid: 8 b x 16 jc x 8 ic = 1024 blocks.
// ---------------------------------------------------------------------------
__global__ void reduce_kernel(float* __restrict__ d_out) {
    __shared__ float4 sb[2][256];
    __shared__ float stv[8], smse[8];

    int tid = threadIdx.x;
    int k4  = tid & 31;          // z quad == lane: z = 4*k4 .. 4*k4+3
    int jl  = tid >> 5;          // 0..7 local j (warp id)
    int bx  = blockIdx.x;
    int b   = bx >> 7;           // 128 blocks per batch
    int jc  = (bx >> 3) & 15;
    int ic  = bx & 7;
    int i0  = ic << 4;
    int j0  = jc << 3;

    const float* colp = g_grid + ((size_t)b << 21) + ((j0 + jl) << 7) + (k4 << 2);

    float tv = 0.f, mse = 0.f;
    float4 prev = make_float4(0.f, 0.f, 0.f, 0.f);
    bool top    = (jl == 7);
    bool have_y = (!top) || (j0 + 8 <= 127);     // jc==15, jl==7 -> global edge

    #pragma unroll 1
    for (int ii = 0; ii <= 16; ii++) {
        int i = i0 + ii;
        if (i > 127) break;                      // uniform across block
        const float* p = colp + (i << 14);
        float4 g = *reinterpret_cast<const float4*>(p);

        if (ii > 0) {                            // x-diffs (planes i-1, i)
            float d;
            d = g.x - prev.x; tv += fabsf(d); mse = fmaf(d, d, mse);
            d = g.y - prev.y; tv += fabsf(d); mse = fmaf(d, d, mse);
            d = g.z - prev.z; tv += fabsf(d); mse = fmaf(d, d, mse);
            d = g.w - prev.w; tv += fabsf(d); mse = fmaf(d, d, mse);
        }
        prev = g;

        if (ii < 16) {                           // owned plane: y + z diffs
            float4* s = sb[ii & 1];
            s[tid] = g;

            // z-seam: next quad's .x is one lane over
            float nx = __shfl_down_sync(0xffffffffu, g.x, 1);

            float4 yn = make_float4(0.f, 0.f, 0.f, 0.f);
            if (top && have_y)                   // halo row from next j-chunk
                yn = *reinterpret_cast<const float4*>(p + 128);
            __syncthreads();

            float d;
            // z-diffs internal to the quad
            d = g.y - g.x; tv += fabsf(d); mse = fmaf(d, d, mse);
            d = g.z - g.y; tv += fabsf(d); mse = fmaf(d, d, mse);
            d = g.w - g.z; tv += fabsf(d); mse = fmaf(d, d, mse);
            if (k4 < 31) {
                d = nx - g.w; tv += fabsf(d); mse = fmaf(d, d, mse);
            }
            // y-diffs: row jl+1 from shared, halo row for jl==7
            if (!top) yn = s[tid + 32];
            if (have_y) {
                d = yn.x - g.x; tv += fabsf(d); mse = fmaf(d, d, mse);
                d = yn.y - g.y; tv += fabsf(d); mse = fmaf(d, d, mse);
                d = yn.z - g.z; tv += fabsf(d); mse = fmaf(d, d, mse);
                d = yn.w - g.w; tv += fabsf(d); mse = fmaf(d, d, mse);
            }
        }
    }

    // block reduction: warp shuffle -> shared -> single atomicAdd
    #pragma unroll
    for (int o = 16; o; o >>= 1) {
        tv  += __shfl_down_sync(0xffffffffu, tv,  o);
        mse += __shfl_down_sync(0xffffffffu, mse, o);
    }
    int lane = tid & 31, w = tid >> 5;
    if (lane == 0) { stv[w] = tv; smse[w] = mse; }
    __syncthreads();
    if (tid == 0) {
        float TV = 0.f, MS = 0.f;
        #pragma unroll
        for (int q = 0; q < 8; q++) { TV += stv[q]; MS += smse[q]; }
        const float inv_tv  = 1.f / 2097152.f;   // xsize^3
        const float inv_mse = 1.f / 32512.f;     // 2*128*128 - 2*128
        atomicAdd(&d_out[b],     TV * inv_tv);
        atomicAdd(&d_out[8 + b], MS * inv_mse);
    }
}

// ---------------------------------------------------------------------------
extern "C" void kernel_launch(void* const* d_in, const int* in_sizes, int n_in,
                              void* d_out, int out_size) {
    const int4*   idx4 = (const int4*)d_in[0];    // [B, N, 3] int32
    const float4* val4 = (const float4*)d_in[1];  // [B, N] float32
    float* out = (float*)d_out;                   // tv[8] ++ mse[8]

    void* grid_ptr = nullptr;
    cudaGetSymbolAddress(&grid_ptr, g_grid);

    cudaMemsetAsync(grid_ptr, 0, (size_t)GRID_ELEMS * sizeof(float));
    cudaMemsetAsync(out, 0, (size_t)out_size * sizeof(float));
    scatter_kernel<<<2048, 256>>>(idx4, val4);    // 524288 threads x 4 points
    reduce_kernel<<<1024, 256>>>(out);            // 8b x 16jc x 8ic slabs
}

// round 5
// speedup vs baseline: 1.0765x; 1.0765x over previous
#include <cuda_runtime.h>
#include <cstdint>

#define XS 128
#define BATCH 8
#define GRID_ELEMS (BATCH * XS * XS * XS)   // 16,777,216 floats = 67 MB (fits L2)

__device__ __align__(128) float g_grid[GRID_ELEMS];

// ---------------------------------------------------------------------------
// Kernel 1: zero the grid via TMA bulk stores (SMEM -> GMEM), off the LSU.
// 512 blocks x 128 threads; each block: zero 32KB SMEM once, then 4x
// cp.async.bulk of 32KB = 128KB per block. Writes allocate dirty L2 lines.
// Block 0 also zeroes the 16 output accumulators.
// ---------------------------------------------------------------------------
__global__ void zero_tma_kernel(float* __restrict__ d_out, int out_size) {
    __shared__ __align__(16) float zbuf[8192];           // 32 KB of zeros
    int tid = threadIdx.x;
    float4* z4 = reinterpret_cast<float4*>(zbuf);
    float4 z = make_float4(0.f, 0.f, 0.f, 0.f);
    #pragma unroll
    for (int i = 0; i < 16; i++)                         // 128 thr * 16 = 32KB
        z4[tid + (i << 7)] = z;
    if (blockIdx.x == 0 && tid < 16 && tid < out_size) d_out[tid] = 0.f;
    __syncthreads();

    if (tid == 0) {
        asm volatile("fence.proxy.async.shared::cta;" ::: "memory");
        uint32_t saddr;
        asm("{ .reg .u64 t; cvta.to.shared.u64 t, %1; cvt.u32.u64 %0, t; }"
            : "=r"(saddr) : "l"(zbuf));
        char* gbase = reinterpret_cast<char*>(g_grid)
                    + (size_t)blockIdx.x * (4u * 32768u);
        int bytes = 32768;
        #pragma unroll
        for (int c = 0; c < 4; c++) {
            asm volatile(
                "cp.async.bulk.global.shared::cta.bulk_group [%0], [%1], %2;"
                :: "l"(gbase + (size_t)c * 32768u), "r"(saddr), "r"(bytes)
                : "memory");
        }
        asm volatile("cp.async.bulk.commit_group;" ::: "memory");
        asm volatile("cp.async.bulk.wait_group 0;" ::: "memory");
    }
}

// ---------------------------------------------------------------------------
// Kernel 2: scatter-add, 4 points per thread.
// 12 ints per 4 points -> 3x int4, values -> 1x float4.
// __ldcs: stream indices/values through L2 without evicting the grid.
// ---------------------------------------------------------------------------
__global__ void scatter_kernel(const int4* __restrict__ idx4,
                               const float4* __restrict__ val4) {
    int t = blockIdx.x * blockDim.x + threadIdx.x;   // 0 .. 524287
    int b = t >> 16;                                 // 65536 threads per batch
    int4 a = __ldcs(idx4 + 3 * t);                   // x0 y0 z0 x1
    int4 c = __ldcs(idx4 + 3 * t + 1);               // y1 z1 x2 y2
    int4 e = __ldcs(idx4 + 3 * t + 2);               // z2 x3 y3 z3
    float4 v = __ldcs(val4 + t);
    float* gb = g_grid + (b << 21);
    atomicAdd(gb + ((a.x << 14) | (a.y << 7) | a.z), v.x);
    atomicAdd(gb + ((a.w << 14) | (c.x << 7) | c.y), v.y);
    atomicAdd(gb + ((c.z << 14) | (c.w << 7) | e.x), v.z);
    atomicAdd(gb + ((e.y << 14) | (e.z << 7) | e.w), v.w);
}

// ---------------------------------------------------------------------------
// Kernel 3: fused TV + MSE reduction.
// Block = 256 threads = 8 j-rows x 32 z-quads. Loops over 16 i-planes
// (+1 halo). x-diffs from prev-plane register, z-seam via shfl, y-diffs via
// double-buffered shared (+1 halo row). Grid: 8b x 16jc x 8ic = 1024 blocks.
// ---------------------------------------------------------------------------
__global__ void reduce_kernel(float* __restrict__ d_out) {
    __shared__ float4 sb[2][256];
    __shared__ float stv[8], smse[8];

    int tid = threadIdx.x;
    int k4  = tid & 31;          // z quad == lane: z = 4*k4 .. 4*k4+3
    int jl  = tid >> 5;          // 0..7 local j (warp id)
    int bx  = blockIdx.x;
    int b   = bx >> 7;           // 128 blocks per batch
    int jc  = (bx >> 3) & 15;
    int ic  = bx & 7;
    int i0  = ic << 4;
    int j0  = jc << 3;

    const float* colp = g_grid + ((size_t)b << 21) + ((j0 + jl) << 7) + (k4 << 2);

    float tv = 0.f, mse = 0.f;
    float4 prev = make_float4(0.f, 0.f, 0.f, 0.f);
    bool top    = (jl == 7);
    bool have_y = (!top) || (j0 + 8 <= 127);     // jc==15, jl==7 -> global edge

    #pragma unroll 1
    for (int ii = 0; ii <= 16; ii++) {
        int i = i0 + ii;
        if (i > 127) break;                      // uniform across block
        const float* p = colp + (i << 14);
        float4 g = *reinterpret_cast<const float4*>(p);

        if (ii > 0) {                            // x-diffs (planes i-1, i)
            float d;
            d = g.x - prev.x; tv += fabsf(d); mse = fmaf(d, d, mse);
            d = g.y - prev.y; tv += fabsf(d); mse = fmaf(d, d, mse);
            d = g.z - prev.z; tv += fabsf(d); mse = fmaf(d, d, mse);
            d = g.w - prev.w; tv += fabsf(d); mse = fmaf(d, d, mse);
        }
        prev = g;

        if (ii < 16) {                           // owned plane: y + z diffs
            float4* s = sb[ii & 1];
            s[tid] = g;

            // z-seam: next quad's .x is one lane over
            float nx = __shfl_down_sync(0xffffffffu, g.x, 1);

            float4 yn = make_float4(0.f, 0.f, 0.f, 0.f);
            if (top && have_y)                   // halo row from next j-chunk
                yn = *reinterpret_cast<const float4*>(p + 128);
            __syncthreads();

            float d;
            // z-diffs internal to the quad
            d = g.y - g.x; tv += fabsf(d); mse = fmaf(d, d, mse);
            d = g.z - g.y; tv += fabsf(d); mse = fmaf(d, d, mse);
            d = g.w - g.z; tv += fabsf(d); mse = fmaf(d, d, mse);
            if (k4 < 31) {
                d = nx - g.w; tv += fabsf(d); mse = fmaf(d, d, mse);
            }
            // y-diffs: row jl+1 from shared, halo row for jl==7
            if (!top) yn = s[tid + 32];
            if (have_y) {
                d = yn.x - g.x; tv += fabsf(d); mse = fmaf(d, d, mse);
                d = yn.y - g.y; tv += fabsf(d); mse = fmaf(d, d, mse);
                d = yn.z - g.z; tv += fabsf(d); mse = fmaf(d, d, mse);
                d = yn.w - g.w; tv += fabsf(d); mse = fmaf(d, d, mse);
            }
        }
    }

    // block reduction: warp shuffle -> shared -> single atomicAdd
    #pragma unroll
    for (int o = 16; o; o >>= 1) {
        tv  += __shfl_down_sync(0xffffffffu, tv,  o);
        mse += __shfl_down_sync(0xffffffffu, mse, o);
    }
    int lane = tid & 31, w = tid >> 5;
    if (lane == 0) { stv[w] = tv; smse[w] = mse; }
    __syncthreads();
    if (tid == 0) {
        float TV = 0.f, MS = 0.f;
        #pragma unroll
        for (int q = 0; q < 8; q++) { TV += stv[q]; MS += smse[q]; }
        const float inv_tv  = 1.f / 2097152.f;   // xsize^3
        const float inv_mse = 1.f / 32512.f;     // 2*128*128 - 2*128
        atomicAdd(&d_out[b],     TV * inv_tv);
        atomicAdd(&d_out[8 + b], MS * inv_mse);
    }
}

// ---------------------------------------------------------------------------
extern "C" void kernel_launch(void* const* d_in, const int* in_sizes, int n_in,
                              void* d_out, int out_size) {
    const int4*   idx4 = (const int4*)d_in[0];    // [B, N, 3] int32
    const float4* val4 = (const float4*)d_in[1];  // [B, N] float32
    float* out = (float*)d_out;                   // tv[8] ++ mse[8]

    zero_tma_kernel<<<512, 128>>>(out, out_size); // 512 x 128KB TMA stores
    scatter_kernel<<<2048, 256>>>(idx4, val4);    // 524288 threads x 4 points
    reduce_kernel<<<1024, 256>>>(out);            // 8b x 16jc x 8ic slabs
}

// round 7
// speedup vs baseline: 1.1949x; 1.1099x over previous
#include <cuda_runtime.h>
#include <cstdint>

#define XS 128
#define BATCH 8
#define GRID_ELEMS (BATCH * XS * XS * XS)   // 16,777,216 floats = 67 MB (fits L2)

__device__ __align__(128) float g_grid[GRID_ELEMS];

// ---------------------------------------------------------------------------
// Kernel 1: zero the grid (2x float4 per thread) + zero the 16 output accums
// (best measured zeroing mechanism: 11.0us; memset and TMA both slower)
// ---------------------------------------------------------------------------
__global__ void zero_kernel(float* __restrict__ d_out, int out_size) {
    int t = blockIdx.x * blockDim.x + threadIdx.x;   // 0 .. 2097151
    float4 z = make_float4(0.f, 0.f, 0.f, 0.f);
    float4* g4 = reinterpret_cast<float4*>(g_grid);
    g4[t]           = z;
    g4[t + 2097152] = z;
    if (t < 16 && t < out_size) d_out[t] = 0.f;
}

// ---------------------------------------------------------------------------
// Kernel 2: scatter-add, 4 points per thread.
// 12 ints per 4 points -> 3x int4, values -> 1x float4.
// __ldcs: stream indices/values through L2 without evicting the grid.
// ---------------------------------------------------------------------------
__global__ void scatter_kernel(const int4* __restrict__ idx4,
                               const float4* __restrict__ val4) {
    int t = blockIdx.x * blockDim.x + threadIdx.x;   // 0 .. 524287
    int b = t >> 16;                                 // 65536 threads per batch
    int4 a = __ldcs(idx4 + 3 * t);                   // x0 y0 z0 x1
    int4 c = __ldcs(idx4 + 3 * t + 1);               // y1 z1 x2 y2
    int4 e = __ldcs(idx4 + 3 * t + 2);               // z2 x3 y3 z3
    float4 v = __ldcs(val4 + t);
    float* gb = g_grid + (b << 21);
    atomicAdd(gb + ((a.x << 14) | (a.y << 7) | a.z), v.x);
    atomicAdd(gb + ((a.w << 14) | (c.x << 7) | c.y), v.y);
    atomicAdd(gb + ((c.z << 14) | (c.w << 7) | e.x), v.z);
    atomicAdd(gb + ((e.y << 14) | (e.z << 7) | e.w), v.w);
}

// ---------------------------------------------------------------------------
// Packed f32x2 diff accumulator: 4 diffs of (a - b) -> tv (two scalar
// accumulators via FADD-with-abs) and mse (two packed f32x2 accumulators).
// Sign of the diff is irrelevant for |d| and d*d, so d = fma(b, -1, a).
// ---------------------------------------------------------------------------
__device__ __forceinline__ void acc4(const float4 a, const float4 bv,
                                     unsigned long long neg1,
                                     float& tv0, float& tv1,
                                     unsigned long long& m2a,
                                     unsigned long long& m2b) {
    unsigned long long axy, azw, bxy, bzw, d0, d1;
    asm("mov.b64 %0, {%1,%2};" : "=l"(axy) : "f"(a.x),  "f"(a.y));
    asm("mov.b64 %0, {%1,%2};" : "=l"(azw) : "f"(a.z),  "f"(a.w));
    asm("mov.b64 %0, {%1,%2};" : "=l"(bxy) : "f"(bv.x), "f"(bv.y));
    asm("mov.b64 %0, {%1,%2};" : "=l"(bzw) : "f"(bv.z), "f"(bv.w));
    asm("fma.rn.f32x2 %0, %1, %2, %3;" : "=l"(d0) : "l"(bxy), "l"(neg1), "l"(axy));
    asm("fma.rn.f32x2 %0, %1, %2, %3;" : "=l"(d1) : "l"(bzw), "l"(neg1), "l"(azw));
    asm("fma.rn.f32x2 %0, %1, %1, %0;" : "+l"(m2a) : "l"(d0));
    asm("fma.rn.f32x2 %0, %1, %1, %0;" : "+l"(m2b) : "l"(d1));
    float e0, e1, e2, e3;
    asm("mov.b64 {%0,%1}, %2;" : "=f"(e0), "=f"(e1) : "l"(d0));
    asm("mov.b64 {%0,%1}, %2;" : "=f"(e2), "=f"(e3) : "l"(d1));
    tv0 += fabsf(e0); tv1 += fabsf(e1);
    tv0 += fabsf(e2); tv1 += fabsf(e3);
}

// ---------------------------------------------------------------------------
// Kernel 3: fused TV + MSE reduction. NO shared memory, NO __syncthreads.
// Block = 256 threads = 8 j-rows x 32 z-quads. 16 owned i-planes + 1 halo.
// x-diffs: register chain (cur vs nxt). y-diffs: direct LDG of row j+1
// (L1-hit for 7/8 warps). z-seam: shfl (lane == z-quad). Fixed trip count,
// clamped halo load -> branch-free, unrollable. 8b x 16jc x 8ic = 1024 blocks.
// ---------------------------------------------------------------------------
__global__ void reduce_kernel(float* __restrict__ d_out) {
    __shared__ float stv[8], smse[8];

    int tid = threadIdx.x;
    int k4  = tid & 31;          // z quad == lane
    int jl  = tid >> 5;          // warp id = local j
    int bx  = blockIdx.x;
    int b   = bx >> 7;
    int jc  = (bx >> 3) & 15;
    int ic  = bx & 7;
    int i0  = ic << 4;
    int j   = (jc << 3) + jl;

    const float* colp = g_grid + ((size_t)b << 21) + (j << 7) + (k4 << 2);
    bool have_y = (j < 127);

    unsigned long long neg1;
    asm("mov.b64 %0, {%1,%2};" : "=l"(neg1) : "f"(-1.0f), "f"(-1.0f));

    float tv0 = 0.f, tv1 = 0.f;
    unsigned long long m2a = 0ull, m2b = 0ull;   // packed {0,0}
    float mse_s = 0.f;                           // scalar (z-diffs)

    float4 cur  = *reinterpret_cast<const float4*>(colp + ((size_t)i0 << 14));
    float4 ycur = make_float4(0.f, 0.f, 0.f, 0.f);
    if (have_y)
        ycur = *reinterpret_cast<const float4*>(colp + 128 + ((size_t)i0 << 14));

    #pragma unroll 4
    for (int ii = 0; ii < 16; ii++) {
        int inext   = i0 + ii + 1;
        bool xvalid = (inext <= 127);            // false only ic=7, ii=15
        int iclamp  = xvalid ? inext : 127;
        float4 nxt = *reinterpret_cast<const float4*>(colp + ((size_t)iclamp << 14));
        float4 ynxt = make_float4(0.f, 0.f, 0.f, 0.f);
        if ((ii < 15) & have_y)
            ynxt = *reinterpret_cast<const float4*>(colp + 128 + ((size_t)inext << 14));

        // z-diffs internal to the quad (scalar)
        float d;
        d = cur.y - cur.x; tv0 += fabsf(d); mse_s = fmaf(d, d, mse_s);
        d = cur.z - cur.y; tv1 += fabsf(d); mse_s = fmaf(d, d, mse_s);
        d = cur.w - cur.z; tv0 += fabsf(d); mse_s = fmaf(d, d, mse_s);
        // z-seam: next quad's .x is one lane over
        float nx = __shfl_down_sync(0xffffffffu, cur.x, 1);
        if (k4 < 31) {
            d = nx - cur.w; tv1 += fabsf(d); mse_s = fmaf(d, d, mse_s);
        }
        // y-diffs (packed)
        if (have_y) acc4(cur, ycur, neg1, tv0, tv1, m2a, m2b);
        // x-diffs (packed)
        if (xvalid) acc4(nxt, cur, neg1, tv0, tv1, m2a, m2b);

        cur = nxt; ycur = ynxt;
    }

    // combine packed + scalar accumulators
    float ma0, ma1, mb0, mb1;
    asm("mov.b64 {%0,%1}, %2;" : "=f"(ma0), "=f"(ma1) : "l"(m2a));
    asm("mov.b64 {%0,%1}, %2;" : "=f"(mb0), "=f"(mb1) : "l"(m2b));
    float tv  = tv0 + tv1;
    float mse = mse_s + (ma0 + ma1) + (mb0 + mb1);

    // block reduction: warp shuffle -> shared -> single atomicAdd
    #pragma unroll
    for (int o = 16; o; o >>= 1) {
        tv  += __shfl_down_sync(0xffffffffu, tv,  o);
        mse += __shfl_down_sync(0xffffffffu, mse, o);
    }
    int lane = tid & 31, w = tid >> 5;
    if (lane == 0) { stv[w] = tv; smse[w] = mse; }
    __syncthreads();
    if (tid == 0) {
        float TV = 0.f, MS = 0.f;
        #pragma unroll
        for (int q = 0; q < 8; q++) { TV += stv[q]; MS += smse[q]; }
        const float inv_tv  = 1.f / 2097152.f;   // xsize^3
        const float inv_mse = 1.f / 32512.f;     // 2*128*128 - 2*128
        atomicAdd(&d_out[b],     TV * inv_tv);
        atomicAdd(&d_out[8 + b], MS * inv_mse);
    }
}

// ---------------------------------------------------------------------------
extern "C" void kernel_launch(void* const* d_in, const int* in_sizes, int n_in,
                              void* d_out, int out_size) {
    const int4*   idx4 = (const int4*)d_in[0];    // [B, N, 3] int32
    const float4* val4 = (const float4*)d_in[1];  // [B, N] float32
    float* out = (float*)d_out;                   // tv[8] ++ mse[8]

    zero_kernel<<<2048, 1024>>>(out, out_size);   // 2M threads x 2 float4
    scatter_kernel<<<2048, 256>>>(idx4, val4);    // 524288 threads x 4 points
    reduce_kernel<<<1024, 256>>>(out);            // 8b x 16jc x 8ic slabs
}